// round 11
// baseline (speedup 1.0000x reference)
#include <cuda_runtime.h>
#include <cstdint>

#define NUM_CLASSES    32000
#define ROW_BYTES      128000
#define ALPHA          0.95f

#define THREADS        544            // 16 consumer warps + 1 producer warp
#define NCONS          512
#define NCW            16
#define PROD_WARP      16

#define CHUNKS_PER_ROW 8
#define CHUNK_BYTES    16000
#define CHUNK_F4       1000           // float4 per chunk
#define NSLOTS         12             // 12 * 16000 = 192000 B prefetch ring

// second f4 per thread exists only for tid < CHUNK_F4 - NCONS = 488
#define SECOND_LIM     (CHUNK_F4 - NCONS)   // 488

// smem layout (dynamic):
//   [0,96)     full mbarriers     (12 x 8B)
//   [128,224)  consumed mbarriers (12 x 8B)
//   [256,320)  swarp[16]
//   [320,324)  sS
//   [324,328)  sT
//   [512, 512+192000) ring slots
#define OFF_FULL     0
#define OFF_CONSUMED 128
#define OFF_SWARP    256
#define OFF_SS       320
#define OFF_ST       324
#define OFF_SLOTS    512
#define SMEM_TOTAL   (OFF_SLOTS + NSLOTS * CHUNK_BYTES)   // 192512

__device__ __forceinline__ uint32_t smem_u32(const void* p) {
    uint32_t a;
    asm("{ .reg .u64 t; cvta.to.shared.u64 t, %1; cvt.u32.u64 %0, t; }"
        : "=r"(a) : "l"(p));
    return a;
}
__device__ __forceinline__ void mbar_init(uint32_t addr, uint32_t cnt) {
    asm volatile("mbarrier.init.shared.b64 [%0], %1;" :: "r"(addr), "r"(cnt) : "memory");
}
__device__ __forceinline__ void mbar_expect_tx(uint32_t addr, uint32_t bytes) {
    asm volatile("mbarrier.arrive.expect_tx.shared.b64 _, [%0], %1;"
                 :: "r"(addr), "r"(bytes) : "memory");
}
__device__ __forceinline__ void mbar_arrive(uint32_t addr) {
    asm volatile("mbarrier.arrive.shared.b64 _, [%0];" :: "r"(addr) : "memory");
}
__device__ __forceinline__ void mbar_wait(uint32_t addr, uint32_t parity) {
    uint32_t done;
    asm volatile(
        "{\n\t.reg .pred p;\n\t"
        "mbarrier.try_wait.parity.acquire.cta.shared::cta.b64 p, [%1], %2;\n\t"
        "selp.b32 %0, 1, 0, p;\n\t}"
        : "=r"(done) : "r"(addr), "r"(parity) : "memory");
    if (!done) {
        asm volatile(
            "{\n\t.reg .pred P1;\n\t"
            "W_%=:\n\t"
            "mbarrier.try_wait.parity.acquire.cta.shared::cta.b64 P1, [%0], %1, 0x989680;\n\t"
            "@P1 bra.uni D_%=;\n\t"
            "bra.uni W_%=;\n\t"
            "D_%=:\n\t}"
            :: "r"(addr), "r"(parity) : "memory");
    }
}
__device__ __forceinline__ void bulk_g2s(uint32_t dst, const void* src,
                                         uint32_t bytes, uint32_t mbar) {
    asm volatile(
        "cp.async.bulk.shared::cluster.global.mbarrier::complete_tx::bytes "
        "[%0], [%1], %2, [%3];"
        :: "r"(dst), "l"(src), "r"(bytes), "r"(mbar) : "memory");
}

extern __shared__ char smem[];

__global__ __launch_bounds__(THREADS, 1)
void smooth_kernel(const float* __restrict__ in,
                   const int* __restrict__ labels,
                   float* __restrict__ out,
                   int batch)
{
    const uint32_t sbase     = smem_u32(smem);
    const uint32_t full0     = sbase + OFF_FULL;
    const uint32_t consumed0 = sbase + OFF_CONSUMED;
    float* swarp = reinterpret_cast<float*>(smem + OFF_SWARP);
    float* sSp   = reinterpret_cast<float*>(smem + OFF_SS);
    float* sTp   = reinterpret_cast<float*>(smem + OFF_ST);
    char*  slots = smem + OFF_SLOTS;
    const uint32_t slots_u = sbase + OFF_SLOTS;

    const int tid = threadIdx.x;
    const int wid = tid >> 5;
    const int lid = tid & 31;

    if (tid == 0) {
        #pragma unroll
        for (int s = 0; s < NSLOTS; s++) {
            mbar_init(full0     + 8u * s, 1);     // TMA expect_tx completion
            mbar_init(consumed0 + 8u * s, NCW);   // one arrive per consumer warp
        }
    }
    __syncthreads();

    // chunks handled by this CTA
    const int nrows = (batch - blockIdx.x + gridDim.x - 1) / gridDim.x;
    const int T = nrows * CHUNKS_PER_ROW;

    if (wid == PROD_WARP) {
        // --------- loader: pure read-issue stream, never blocks on stores ---------
        if (lid == 0) {
            int slot = 0, wrap = 0;
            for (int c = 0; c < T; c++) {
                if (wrap > 0)   // slot reused: wait until all 16 warps read it
                    mbar_wait(consumed0 + 8u * slot, (uint32_t)((wrap - 1) & 1));
                const int rl = c >> 3;
                const int cc = c & 7;
                const int r  = blockIdx.x + rl * gridDim.x;
                const char* src = reinterpret_cast<const char*>(in)
                                + (size_t)r * ROW_BYTES
                                + (size_t)cc * CHUNK_BYTES;
                mbar_expect_tx(full0 + 8u * slot, CHUNK_BYTES);
                bulk_g2s(slots_u + (uint32_t)slot * CHUNK_BYTES,
                         src, CHUNK_BYTES, full0 + 8u * slot);
                if (++slot == NSLOTS) { slot = 0; wrap++; }
            }
        }
    } else {
        // --- consumers (16 warps / 512 threads): stage row in regs, sum, scale, STG ---
        const bool has2 = (tid < SECOND_LIM);
        int slot = 0, cphase = 0;

        for (int r = blockIdx.x; r < batch; r += gridDim.x) {
            const int label = __ldg(labels + r);
            const int lvec  = label >> 2;            // f4 index within row
            const int lcomp = label & 3;
            const int c_l   = lvec / CHUNK_F4;       // chunk holding label elem
            const int li    = lvec % CHUNK_F4;       // f4 index within chunk
            const int lown  = (li < NCONS) ? li : (li - NCONS);  // owner tid

            float4 d[2 * CHUNKS_PER_ROW];
            float  local = 0.0f;

            // -- sum phase: copy chunk to regs, release slot immediately --
            #pragma unroll
            for (int c = 0; c < CHUNKS_PER_ROW; c++) {
                mbar_wait(full0 + 8u * slot, (uint32_t)cphase);
                const float4* ch =
                    reinterpret_cast<const float4*>(slots + (size_t)slot * CHUNK_BYTES);
                float4 v0 = ch[tid];
                float4 v1 = make_float4(0.f, 0.f, 0.f, 0.f);
                if (has2) v1 = ch[tid + NCONS];
                d[2 * c]     = v0;
                d[2 * c + 1] = v1;
                local += (v0.x + v0.y) + (v0.z + v0.w);
                local += (v1.x + v1.y) + (v1.z + v1.w);
                if (c == c_l && tid == lown) {
                    const float4 vv = (li < NCONS) ? v0 : v1;
                    *sTp = (lcomp == 0) ? vv.x : (lcomp == 1) ? vv.y
                         : (lcomp == 2) ? vv.z : vv.w;
                }
                __syncwarp();
                if (lid == 0) mbar_arrive(consumed0 + 8u * slot);  // slot free NOW
                if (++slot == NSLOTS) { slot = 0; cphase ^= 1; }
            }

            // -- reduce S across 16 warps --
            #pragma unroll
            for (int o = 16; o > 0; o >>= 1)
                local += __shfl_down_sync(0xffffffffu, local, o);
            if (lid == 0) swarp[wid] = local;
            asm volatile("bar.sync 1, %0;" :: "n"(NCONS) : "memory");
            if (wid == 0) {
                float v = (lid < NCW) ? swarp[lid] : 0.0f;
                #pragma unroll
                for (int o = 8; o > 0; o >>= 1)
                    v += __shfl_down_sync(0xffffffffu, v, o);
                if (lid == 0) *sSp = v;
            }
            asm volatile("bar.sync 1, %0;" :: "n"(NCONS) : "memory");

            const float S    = *sSp;
            const float t    = *sTp;
            const float s    = ALPHA / (1.0f + S - 2.0f * t);
            const float corr = 1.0f - s * S;

            // -- scale + store from registers (evict-first streaming stores) --
            float4* orow = reinterpret_cast<float4*>(out + (size_t)r * NUM_CLASSES);
            #pragma unroll
            for (int c = 0; c < CHUNKS_PER_ROW; c++) {
                {
                    const float4 v = d[2 * c];
                    float4 o = make_float4(s * v.x, s * v.y, s * v.z, s * v.w);
                    if (c == c_l && li < NCONS && tid == li) {
                        o.x += (lcomp == 0) ? corr : 0.0f;
                        o.y += (lcomp == 1) ? corr : 0.0f;
                        o.z += (lcomp == 2) ? corr : 0.0f;
                        o.w += (lcomp == 3) ? corr : 0.0f;
                    }
                    __stcs(orow + c * CHUNK_F4 + tid, o);
                }
                if (has2) {
                    const float4 v = d[2 * c + 1];
                    float4 o = make_float4(s * v.x, s * v.y, s * v.z, s * v.w);
                    if (c == c_l && li >= NCONS && tid == li - NCONS) {
                        o.x += (lcomp == 0) ? corr : 0.0f;
                        o.y += (lcomp == 1) ? corr : 0.0f;
                        o.z += (lcomp == 2) ? corr : 0.0f;
                        o.w += (lcomp == 3) ? corr : 0.0f;
                    }
                    __stcs(orow + c * CHUNK_F4 + tid + NCONS, o);
                }
            }
        }
    }
}

extern "C" void kernel_launch(void* const* d_in, const int* in_sizes, int n_in,
                              void* d_out, int out_size)
{
    const float* logits = (const float*)d_in[0];
    const int*   labels = (const int*)d_in[1];
    float*       out    = (float*)d_out;

    const int batch = in_sizes[1];

    cudaFuncSetAttribute(smooth_kernel,
                         cudaFuncAttributeMaxDynamicSharedMemorySize, SMEM_TOTAL);

    int dev = 0, sms = 148;
    cudaGetDevice(&dev);
    cudaDeviceGetAttribute(&sms, cudaDevAttrMultiProcessorCount, dev);
    int grid = sms < batch ? sms : batch;

    smooth_kernel<<<grid, THREADS, SMEM_TOTAL>>>(logits, labels, out, batch);
}